// round 9
// baseline (speedup 1.0000x reference)
#include <cuda_runtime.h>
#include <float.h>
#include <math.h>

#define MAXT 8192
#define NB   128          // direction bins == grid size of mega kernel
#define CAP  128          // max key candidates per bin (expect ~2-8)
#define CAPQ 768          // max queries per bin list (expect ~64, skew ~3x; exact fallback)
#define BTH  512
#define NWRP (BTH / 32)
#define PD   36
#define RPB  (MAXT / NB)  // 64 rows projected per block

// Device scratch (graph-capturable: no allocs). g_qcnt self-resets each
// launch; g_bar is a cumulative barrier counter (monotone across replays);
// partial-max arrays are fully rewritten before use every launch.
__device__ ulonglong2 g_QQ[MAXT], g_KK[MAXT];
__device__ unsigned g_binPS[MAXT];
__device__ float g_Vop[MAXT], g_Varg[MAXT], g_Vstk[MAXT];
__device__ int g_qcnt[2 * NB];
__device__ int g_qlistP[NB * CAPQ], g_qlistS[NB * CAPQ];
__device__ float g_sPartP[NB * NB], g_sPartS[NB * NB];   // [bin*NB + block]
__device__ float g_n2P[NB], g_n2S[NB];                   // per-block |k|^2 max
__device__ unsigned int g_bar;

__device__ __forceinline__ unsigned long long packf2(float lo, float hi) {
    return ((unsigned long long)__float_as_uint(hi) << 32) | (unsigned long long)__float_as_uint(lo);
}
__device__ __forceinline__ float lo32(unsigned long long v) { return __uint_as_float((unsigned)v); }
__device__ __forceinline__ float hi32(unsigned long long v) { return __uint_as_float((unsigned)(v >> 32)); }

__device__ __forceinline__ unsigned long long mul2(unsigned long long a, unsigned long long b) {
    unsigned long long r;
    asm("mul.rn.f32x2 %0, %1, %2;" : "=l"(r) : "l"(a), "l"(b));
    return r;
}
__device__ __forceinline__ unsigned long long fma2(unsigned long long a, unsigned long long b, unsigned long long c) {
    unsigned long long r;
    asm("fma.rn.f32x2 %0, %1, %2, %3;" : "=l"(r) : "l"(a), "l"(b), "l"(c));
    return r;
}

#define PI_F 3.14159265358979f
#define TWO_PI_F 6.2831853071795865f

__device__ __forceinline__ unsigned qbins(float qpx, float qpy, float qsx, float qsy) {
    const float SC = NB / TWO_PI_F;
    int bP = (int)((atan2f(qpy, qpx) + PI_F) * SC);
    bP = min(max(bP, 0), NB - 1);
    int bS = (int)((atan2f(qsy, qsx) + PI_F) * SC);
    bS = min(max(bS, 0), NB - 1);
    return (unsigned)bP | ((unsigned)bS << 16);
}

__device__ __forceinline__ void push_query(int i, unsigned bp) {
    const int bP = (int)(bp & 0xffffu), bS = (int)(bp >> 16);
    int p = atomicAdd(&g_qcnt[bP], 1);
    if (p < CAPQ) g_qlistP[bP * CAPQ + p] = i;
    int s = atomicAdd(&g_qcnt[NB + bS], 1);
    if (s < CAPQ) g_qlistS[bS * CAPQ + s] = i;
}

// Device-wide barrier: valid because grid (128) <= SM count (148+) => all
// blocks resident in wave 1. Arrival via one atomicAdd; POLLING via plain
// volatile loads (L2 broadcast reads; no atomic-ALU serialization).
// Cumulative counter: monotone across graph replays, no reset needed.
__device__ __forceinline__ void grid_sync() {
    __syncthreads();
    __threadfence();
    if (threadIdx.x == 0) {
        const unsigned G = gridDim.x;
        unsigned t = atomicAdd(&g_bar, 1u);
        unsigned target = (t / G + 1u) * G;
        while (*(volatile unsigned*)&g_bar < target) { __nanosleep(32); }
        __threadfence();
    }
    __syncthreads();
}

// ---------------------------------------------------------------------------
// MEGA kernel (D==36, T==MAXT). One block per direction bin.
//  Phase 1: project 64 rows; push query ids to per-bin lists; compute this
//    block's per-bin directional max over ITS OWN 64 keys for ALL bins
//    (smem-only ALU work) + per-block |k|^2 max; plain-store partials.
//  grid_sync.
//  Phase 2: reduce 128 partials -> exact global max M and Kmax^2 for bin b
//    (identical value to a full scan: max of maxes). Threshold
//    M - 1.25*Kmax*DLT (round-4-proven exact cover). ONE batched full-T
//    collect scan (8-wide MLP). Resolve own bin's queries from lists.
// ---------------------------------------------------------------------------
__global__ __launch_bounds__(BTH) void mega_kernel(
        const float* __restrict__ emb,
        const float* __restrict__ wqp, const float* __restrict__ wkp,
        const float* __restrict__ wvop, const float* __restrict__ wvarg,
        const float* __restrict__ wqs, const float* __restrict__ wks,
        const float* __restrict__ wvs, float* __restrict__ out) {
    __shared__ float sw[11 * PD];
    __shared__ float se[RPB * PD];
    __shared__ ulonglong2 sKxy[RPB];
    __shared__ int scandP[CAP], scandS[CAP];
    __shared__ ulonglong2 sKP[CAP], sKS[CAP];
    __shared__ float sVop[CAP], sVarg[CAP], sVstk[CAP];
    __shared__ int scnt[2];
    __shared__ float sredP[4], sredS[4], sredNP[4], sredNS[4];
    __shared__ float sn2w[2][2];
    __shared__ float sth[2];

    const int b = blockIdx.x;
    const int tid = threadIdx.x, lane = tid & 31, w = tid >> 5;
    const int T = MAXT;
    const float DLT = TWO_PI_F / NB;

    // ================= phase 1: projection of rows [b*RPB, (b+1)*RPB) =======
    for (int k = tid; k < 2 * PD; k += BTH) {
        sw[k]          = wqp[k];
        sw[2 * PD + k] = wkp[k];
        sw[4 * PD + k] = wqs[k];
        sw[6 * PD + k] = wks[k];
    }
    if (tid < PD) {
        sw[8 * PD + tid]  = wvop[tid];
        sw[9 * PD + tid]  = wvarg[tid];
        sw[10 * PD + tid] = wvs[tid];
    }
    const int base = b * RPB;
    {
        const float4* emb4 = (const float4*)(emb + (size_t)base * PD);
        if (tid < RPB * PD / 4) ((float4*)se)[tid] = emb4[tid];
        int idx = tid + BTH;
        if (idx < RPB * PD / 4) ((float4*)se)[idx] = emb4[idx];
    }
    __syncthreads();

    if (tid < RPB * 4) {
        const int row = tid >> 2, part = tid & 3;
        const float* r0 = se + row * PD + part * 9;
        float rv[9];
#pragma unroll
        for (int dd = 0; dd < 9; dd++) rv[dd] = r0[dd];
        // c: 0=Qp.x 1=Qp.y 2=Kp.x 3=Kp.y 4=Qs.x 5=Qs.y 6=Ks.x 7=Ks.y 8=Vop 9=Varg 10=Vstk
        float a[11];
#pragma unroll
        for (int c = 0; c < 11; c++) a[c] = 0.f;
#pragma unroll
        for (int c = 0; c < 11; c++) {
            const float* wc = sw + c * PD + part * 9;
#pragma unroll
            for (int dd = 0; dd < 9; dd++) a[c] = fmaf(rv[dd], wc[dd], a[c]);
        }
#pragma unroll
        for (int c = 0; c < 11; c++) {
            a[c] += __shfl_down_sync(0xffffffffu, a[c], 1);
            a[c] += __shfl_down_sync(0xffffffffu, a[c], 2);
        }
        if (part == 0) {
            int i = base + row;
            ulonglong2 kk = make_ulonglong2(packf2(a[2], a[6]), packf2(a[3], a[7]));
            g_QQ[i] = make_ulonglong2(packf2(a[0], a[4]), packf2(a[1], a[5]));
            g_KK[i] = kk;
            sKxy[row] = kk;
            unsigned bp = qbins(a[0], a[1], a[4], a[5]);
            g_binPS[i] = bp;
            g_Vop[i] = a[8]; g_Varg[i] = a[9]; g_Vstk[i] = a[10];
            push_query(i, bp);
        }
    }
    __syncthreads();

    // ---- per-bin partial max over this block's 64 keys (ALL bins) ----
    {
        const int mybin = tid >> 2, q = tid & 3;      // 128 bins x 4 threads
        const float thc = -PI_F + (mybin + 0.5f) * DLT;
        const float ux = cosf(thc), uy = sinf(thc);
        const unsigned long long ua = packf2(ux, ux), ub = packf2(uy, uy);
        float mP = -FLT_MAX, mS = -FLT_MAX;
#pragma unroll
        for (int k = 0; k < RPB / 4; k++) {
            ulonglong2 kk = sKxy[q * (RPB / 4) + k];
            unsigned long long s = fma2(ua, kk.x, mul2(ub, kk.y));
            mP = fmaxf(mP, lo32(s));
            mS = fmaxf(mS, hi32(s));
        }
        mP = fmaxf(mP, __shfl_down_sync(0xffffffffu, mP, 1));
        mS = fmaxf(mS, __shfl_down_sync(0xffffffffu, mS, 1));
        mP = fmaxf(mP, __shfl_down_sync(0xffffffffu, mP, 2));
        mS = fmaxf(mS, __shfl_down_sync(0xffffffffu, mS, 2));
        if (q == 0) {
            g_sPartP[mybin * NB + b] = mP;
            g_sPartS[mybin * NB + b] = mS;
        }
    }
    // ---- per-block |k|^2 max (both heads) ----
    if (tid < RPB) {
        ulonglong2 kk = sKxy[tid];
        unsigned long long n2 = fma2(kk.x, kk.x, mul2(kk.y, kk.y));
        float np = lo32(n2), ns = hi32(n2);
#pragma unroll
        for (int off = 16; off; off >>= 1) {
            np = fmaxf(np, __shfl_xor_sync(0xffffffffu, np, off));
            ns = fmaxf(ns, __shfl_xor_sync(0xffffffffu, ns, off));
        }
        if (lane == 0) { sn2w[0][tid >> 5] = np; sn2w[1][tid >> 5] = ns; }
    }
    __syncthreads();
    if (tid == 0) {
        g_n2P[b] = fmaxf(sn2w[0][0], sn2w[0][1]);
        g_n2S[b] = fmaxf(sn2w[1][0], sn2w[1][1]);
    }

    // ================= device-wide sync =====================================
    grid_sync();

    // ================= phase 2: threshold from partials =====================
    const float thb = -PI_F + (b + 0.5f) * DLT;
    const float ux = cosf(thb), uy = sinf(thb);
    const unsigned long long ua = packf2(ux, ux), ub = packf2(uy, uy);

    if (tid < 2) scnt[tid] = 0;
    if (tid < NB) {
        float vp = g_sPartP[b * NB + tid];
        float vs = g_sPartS[b * NB + tid];
        float np = g_n2P[tid];
        float ns = g_n2S[tid];
#pragma unroll
        for (int off = 16; off; off >>= 1) {
            vp = fmaxf(vp, __shfl_xor_sync(0xffffffffu, vp, off));
            vs = fmaxf(vs, __shfl_xor_sync(0xffffffffu, vs, off));
            np = fmaxf(np, __shfl_xor_sync(0xffffffffu, np, off));
            ns = fmaxf(ns, __shfl_xor_sync(0xffffffffu, ns, off));
        }
        if (lane == 0) { sredP[w] = vp; sredS[w] = vs; sredNP[w] = np; sredNS[w] = ns; }
    }
    __syncthreads();
    if (tid == 0) {
        float MP = fmaxf(fmaxf(sredP[0], sredP[1]), fmaxf(sredP[2], sredP[3]));
        float MS = fmaxf(fmaxf(sredS[0], sredS[1]), fmaxf(sredS[2], sredS[3]));
        float NP = fmaxf(fmaxf(sredNP[0], sredNP[1]), fmaxf(sredNP[2], sredNP[3]));
        float NS = fmaxf(fmaxf(sredNS[0], sredNS[1]), fmaxf(sredNS[2], sredNS[3]));
        sth[0] = MP - 1.25f * sqrtf(NP) * DLT;   // exact-cover threshold
        sth[1] = MS - 1.25f * sqrtf(NS) * DLT;
    }
    __syncthreads();
    const float tP = sth[0], tS = sth[1];

    // ================= collect: ONE batched full-T scan =====================
#pragma unroll
    for (int g = 0; g < MAXT / BTH / 8; g++) {
        ulonglong2 kb[8];
#pragma unroll
        for (int u = 0; u < 8; u++) kb[u] = g_KK[tid + (g * 8 + u) * BTH];
#pragma unroll
        for (int u = 0; u < 8; u++) {
            const int j = tid + (g * 8 + u) * BTH;
            unsigned long long s = fma2(ua, kb[u].x, mul2(ub, kb[u].y));
            if (lo32(s) >= tP) { int p = atomicAdd(&scnt[0], 1); if (p < CAP) scandP[p] = j; }
            if (hi32(s) >= tS) { int p = atomicAdd(&scnt[1], 1); if (p < CAP) scandS[p] = j; }
        }
    }
    __syncthreads();
    const int nP = min(scnt[0], CAP), nS = min(scnt[1], CAP);
    for (int t = tid; t < nP; t += BTH) {
        int c = scandP[t];
        sKP[t] = g_KK[c]; sVop[t] = g_Vop[c]; sVarg[t] = g_Varg[c];
    }
    for (int t = tid; t < nS; t += BTH) {
        int c = scandS[t];
        sKS[t] = g_KK[c]; sVstk[t] = g_Vstk[c];
    }
    __syncthreads();

    // ================= resolve this bin's queries ===========================
    const int totP = g_qcnt[b], totS = g_qcnt[NB + b];
    const int nqP = min(totP, CAPQ), nqS = min(totS, CAPQ);

    for (int t = tid; t < nqP; t += BTH) {
        const int i = g_qlistP[b * CAPQ + t];
        ulonglong2 q = g_QQ[i];
        const float qx = lo32(q.x), qy = lo32(q.y);
        float best = -FLT_MAX; int bi = 0x7fffffff, bt = 0;
        for (int c = 0; c < nP; c++) {
            int kj = scandP[c];
            ulonglong2 k2 = sKP[c];
            float sc = fmaf(qx, lo32(k2.x), __fmul_rn(qy, lo32(k2.y)));
            if (sc > best || (sc == best && kj < bi)) { best = sc; bi = kj; bt = c; }
        }
        out[i]     = sVop[bt];
        out[T + i] = sVarg[bt];
    }
    for (int t = tid; t < nqS; t += BTH) {
        const int i = g_qlistS[b * CAPQ + t];
        ulonglong2 q = g_QQ[i];
        const float qx = hi32(q.x), qy = hi32(q.y);
        float best = -FLT_MAX; int bi = 0x7fffffff, bt = 0;
        for (int c = 0; c < nS; c++) {
            int kj = scandS[c];
            ulonglong2 k2 = sKS[c];
            float sc = fmaf(qx, hi32(k2.x), __fmul_rn(qy, hi32(k2.y)));
            if (sc > best || (sc == best && kj < bi)) { best = sc; bi = kj; bt = c; }
        }
        out[2 * T + i] = sVstk[bt];
    }

    // exact fallback if a query list overflowed (idempotent rewrites)
    if (totP > CAPQ) {
        for (int j = tid; j < T; j += BTH) {
            if ((g_binPS[j] & 0xffffu) == (unsigned)b) {
                ulonglong2 q = g_QQ[j];
                const float qx = lo32(q.x), qy = lo32(q.y);
                float best = -FLT_MAX; int bi = 0x7fffffff, bt = 0;
                for (int c = 0; c < nP; c++) {
                    int kj = scandP[c];
                    ulonglong2 k2 = sKP[c];
                    float sc = fmaf(qx, lo32(k2.x), __fmul_rn(qy, lo32(k2.y)));
                    if (sc > best || (sc == best && kj < bi)) { best = sc; bi = kj; bt = c; }
                }
                out[j]     = sVop[bt];
                out[T + j] = sVarg[bt];
            }
        }
    }
    if (totS > CAPQ) {
        for (int j = tid; j < T; j += BTH) {
            if ((g_binPS[j] >> 16) == (unsigned)b) {
                ulonglong2 q = g_QQ[j];
                const float qx = hi32(q.x), qy = hi32(q.y);
                float best = -FLT_MAX; int bi = 0x7fffffff, bt = 0;
                for (int c = 0; c < nS; c++) {
                    int kj = scandS[c];
                    ulonglong2 k2 = sKS[c];
                    float sc = fmaf(qx, hi32(k2.x), __fmul_rn(qy, hi32(k2.y)));
                    if (sc > best || (sc == best && kj < bi)) { best = sc; bi = kj; bt = c; }
                }
                out[2 * T + j] = sVstk[bt];
            }
        }
    }

    __syncthreads();
    if (tid == 0) { g_qcnt[b] = 0; g_qcnt[NB + b] = 0; }   // self-reset
}

// ---------------------------------------------------------------------------
// Generic fallback path (D != 36 or T != MAXT): two-kernel pipeline.
// ---------------------------------------------------------------------------
__global__ void proj_generic_kernel(
        const float* __restrict__ emb,
        const float* __restrict__ wqp, const float* __restrict__ wkp,
        const float* __restrict__ wvop, const float* __restrict__ wvarg,
        const float* __restrict__ wqs, const float* __restrict__ wks,
        const float* __restrict__ wvs, int T, int D) {
    extern __shared__ float sw[];
    const int tid = threadIdx.x;
    for (int k = tid; k < 2 * D; k += blockDim.x) {
        sw[k]         = wqp[k];
        sw[2 * D + k] = wkp[k];
        sw[4 * D + k] = wqs[k];
        sw[6 * D + k] = wks[k];
    }
    for (int k = tid; k < D; k += blockDim.x) {
        sw[8 * D + k]  = wvop[k];
        sw[9 * D + k]  = wvarg[k];
        sw[10 * D + k] = wvs[k];
    }
    __syncthreads();
    int i = blockIdx.x * blockDim.x + tid;
    if (i >= T) return;
    const float* e = emb + (size_t)i * D;
    float a[11];
#pragma unroll
    for (int c = 0; c < 11; c++) a[c] = 0.f;
    for (int d = 0; d < D; d++) {
        float ev = e[d];
#pragma unroll
        for (int c = 0; c < 11; c++) a[c] = fmaf(ev, sw[c * D + d], a[c]);
    }
    g_QQ[i] = make_ulonglong2(packf2(a[0], a[4]), packf2(a[1], a[5]));
    g_KK[i] = make_ulonglong2(packf2(a[2], a[6]), packf2(a[3], a[7]));
    unsigned bp = qbins(a[0], a[1], a[4], a[5]);
    g_binPS[i] = bp;
    g_Vop[i] = a[8]; g_Varg[i] = a[9]; g_Vstk[i] = a[10];
    push_query(i, bp);
}

__global__ __launch_bounds__(BTH) void build_query_kernel(float* __restrict__ out, int T) {
    __shared__ int scandP[CAP], scandS[CAP];
    __shared__ float sVop[CAP], sVarg[CAP], sVstk[CAP];
    __shared__ int scnt[2];
    __shared__ float sred[4][NWRP];
    __shared__ float sth[2];

    const int b = blockIdx.x;
    const int tid = threadIdx.x, lane = tid & 31, w = tid >> 5;
    const float DLT = TWO_PI_F / NB;
    const float thb = -PI_F + (b + 0.5f) * DLT;
    const float ux = cosf(thb), uy = sinf(thb);
    const unsigned long long ua = packf2(ux, ux), ub = packf2(uy, uy);

    float v[4] = {-FLT_MAX, -FLT_MAX, 0.f, 0.f};
#pragma unroll 4
    for (int j = tid; j < T; j += BTH) {
        ulonglong2 kk = g_KK[j];
        unsigned long long s  = fma2(ua, kk.x, mul2(ub, kk.y));
        unsigned long long n2 = fma2(kk.x, kk.x, mul2(kk.y, kk.y));
        v[0] = fmaxf(v[0], lo32(s));  v[1] = fmaxf(v[1], hi32(s));
        v[2] = fmaxf(v[2], lo32(n2)); v[3] = fmaxf(v[3], hi32(n2));
    }
#pragma unroll
    for (int c = 0; c < 4; c++) {
#pragma unroll
        for (int off = 16; off; off >>= 1)
            v[c] = fmaxf(v[c], __shfl_xor_sync(0xffffffffu, v[c], off));
        if (lane == 0) sred[c][w] = v[c];
    }
    if (tid < 2) scnt[tid] = 0;
    __syncthreads();
    if (tid < 2) {
        float M = sred[tid][0], N2 = sred[2 + tid][0];
#pragma unroll
        for (int k = 1; k < NWRP; k++) {
            M = fmaxf(M, sred[tid][k]);
            N2 = fmaxf(N2, sred[2 + tid][k]);
        }
        sth[tid] = M - 1.25f * sqrtf(N2) * DLT;
    }
    __syncthreads();
    const float tP = sth[0], tS = sth[1];

#pragma unroll 4
    for (int j = tid; j < T; j += BTH) {
        ulonglong2 kk = g_KK[j];
        unsigned long long s = fma2(ua, kk.x, mul2(ub, kk.y));
        if (lo32(s) >= tP) { int p = atomicAdd(&scnt[0], 1); if (p < CAP) scandP[p] = j; }
        if (hi32(s) >= tS) { int p = atomicAdd(&scnt[1], 1); if (p < CAP) scandS[p] = j; }
    }
    __syncthreads();
    const int nP = min(scnt[0], CAP), nS = min(scnt[1], CAP);
    for (int t = tid; t < nP; t += BTH) {
        int c = scandP[t];
        sVop[t] = g_Vop[c]; sVarg[t] = g_Varg[c];
    }
    for (int t = tid; t < nS; t += BTH) sVstk[t] = g_Vstk[scandS[t]];
    __syncthreads();

    const int totP = g_qcnt[b], totS = g_qcnt[NB + b];
    const int nqP = min(totP, CAPQ), nqS = min(totS, CAPQ);

    for (int t = tid; t < nqP; t += BTH) {
        const int i = g_qlistP[b * CAPQ + t];
        ulonglong2 q = g_QQ[i];
        const float qx = lo32(q.x), qy = lo32(q.y);
        float best = -FLT_MAX; int bi = 0x7fffffff, bt = 0;
        for (int c = 0; c < nP; c++) {
            int kj = scandP[c];
            ulonglong2 k2 = g_KK[kj];
            float sc = fmaf(qx, lo32(k2.x), __fmul_rn(qy, lo32(k2.y)));
            if (sc > best || (sc == best && kj < bi)) { best = sc; bi = kj; bt = c; }
        }
        out[i]     = sVop[bt];
        out[T + i] = sVarg[bt];
    }
    for (int t = tid; t < nqS; t += BTH) {
        const int i = g_qlistS[b * CAPQ + t];
        ulonglong2 q = g_QQ[i];
        const float qx = hi32(q.x), qy = hi32(q.y);
        float best = -FLT_MAX; int bi = 0x7fffffff, bt = 0;
        for (int c = 0; c < nS; c++) {
            int kj = scandS[c];
            ulonglong2 k2 = g_KK[kj];
            float sc = fmaf(qx, hi32(k2.x), __fmul_rn(qy, hi32(k2.y)));
            if (sc > best || (sc == best && kj < bi)) { best = sc; bi = kj; bt = c; }
        }
        out[2 * T + i] = sVstk[bt];
    }

    if (totP > CAPQ) {
        for (int j = tid; j < T; j += BTH) {
            if ((g_binPS[j] & 0xffffu) == (unsigned)b) {
                ulonglong2 q = g_QQ[j];
                const float qx = lo32(q.x), qy = lo32(q.y);
                float best = -FLT_MAX; int bi = 0x7fffffff, bt = 0;
                for (int c = 0; c < nP; c++) {
                    int kj = scandP[c];
                    ulonglong2 k2 = g_KK[kj];
                    float sc = fmaf(qx, lo32(k2.x), __fmul_rn(qy, lo32(k2.y)));
                    if (sc > best || (sc == best && kj < bi)) { best = sc; bi = kj; bt = c; }
                }
                out[j]     = sVop[bt];
                out[T + j] = sVarg[bt];
            }
        }
    }
    if (totS > CAPQ) {
        for (int j = tid; j < T; j += BTH) {
            if ((g_binPS[j] >> 16) == (unsigned)b) {
                ulonglong2 q = g_QQ[j];
                const float qx = hi32(q.x), qy = hi32(q.y);
                float best = -FLT_MAX; int bi = 0x7fffffff, bt = 0;
                for (int c = 0; c < nS; c++) {
                    int kj = scandS[c];
                    ulonglong2 k2 = g_KK[kj];
                    float sc = fmaf(qx, hi32(k2.x), __fmul_rn(qy, hi32(k2.y)));
                    if (sc > best || (sc == best && kj < bi)) { best = sc; bi = kj; bt = c; }
                }
                out[2 * T + j] = sVstk[bt];
            }
        }
    }

    __syncthreads();
    if (tid == 0) { g_qcnt[b] = 0; g_qcnt[NB + b] = 0; }
}

extern "C" void kernel_launch(void* const* d_in, const int* in_sizes, int n_in,
                              void* d_out, int out_size) {
    const float* emb   = (const float*)d_in[0];
    const float* wqp   = (const float*)d_in[1];
    const float* wkp   = (const float*)d_in[2];
    const float* wvop  = (const float*)d_in[3];
    const float* wvarg = (const float*)d_in[4];
    const float* wqs   = (const float*)d_in[5];
    const float* wks   = (const float*)d_in[6];
    const float* wvs   = (const float*)d_in[7];
    float* out = (float*)d_out;

    const int D = in_sizes[1] / 2;   // WQ_prog is (2, D)
    const int T = in_sizes[0] / D;   // embeddings is (T, D)

    if (D == PD && T == MAXT) {
        mega_kernel<<<NB, BTH>>>(emb, wqp, wkp, wvop, wvarg, wqs, wks, wvs, out);
    } else {
        const int pb = (T + 255) / 256;
        proj_generic_kernel<<<pb, 256, (size_t)(11 * D) * sizeof(float)>>>(
            emb, wqp, wkp, wvop, wvarg, wqs, wks, wvs, T, D);
        build_query_kernel<<<NB, BTH>>>(out, T);
    }
}